// round 5
// baseline (speedup 1.0000x reference)
#include <cuda_runtime.h>

// out[i, c] = max_{k<7} x[hex_idx[i,k], c]  for i < L = out_size / 512
// hex_idx is int32 on disk (JAX downgrades int64 without x64 mode).
//
// At the LTS traffic floor (~168MB through L2 @ ~11.3TB/s). This round trims
// scheduling overhead: persistent grid-stride (exactly one wave of 148x8 CTAs),
// 32-bit address math (j*2048 < 2^31), loop-level load/compute overlap.
// Gathers: 256-bit ld.global.nc.L2::evict_last; stores: st.global.cs.

static constexpr int K = 7;

struct F8 { float f[8]; };

__device__ __forceinline__ F8 ldg_el_256(const char* base, unsigned off) {
    unsigned long long r0, r1, r2, r3;
    asm("ld.global.nc.L2::evict_last.v4.b64 {%0,%1,%2,%3}, [%4];"
        : "=l"(r0), "=l"(r1), "=l"(r2), "=l"(r3)
        : "l"(base + off));
    F8 v;
    v.f[0] = __uint_as_float((unsigned)(r0 & 0xffffffffu));
    v.f[1] = __uint_as_float((unsigned)(r0 >> 32));
    v.f[2] = __uint_as_float((unsigned)(r1 & 0xffffffffu));
    v.f[3] = __uint_as_float((unsigned)(r1 >> 32));
    v.f[4] = __uint_as_float((unsigned)(r2 & 0xffffffffu));
    v.f[5] = __uint_as_float((unsigned)(r2 >> 32));
    v.f[6] = __uint_as_float((unsigned)(r3 & 0xffffffffu));
    v.f[7] = __uint_as_float((unsigned)(r3 >> 32));
    return v;
}

__device__ __forceinline__ void stg_cs_128(float* p, float a, float b, float c, float d) {
    asm volatile("st.global.cs.v4.f32 [%0], {%1,%2,%3,%4};"
                 :: "l"(p), "f"(a), "f"(b), "f"(c), "f"(d)
                 : "memory");
}

__global__ void __launch_bounds__(128)
hex_pool_kernel(const char* __restrict__ x,      // (N, 2048 bytes) rows
                const int*  __restrict__ hex_idx,
                float*      __restrict__ out,    // (L, 512) floats
                int L)
{
    // Row-pair decomposition: threads 0..63 -> row 2p, 64..127 -> row 2p+1.
    const int half = threadIdx.x >> 6;     // 0 or 1
    const int c    = threadIdx.x & 63;     // 32B chunk within row
    const unsigned coff = (unsigned)c * 32u;
    const int P = (L + 1) >> 1;            // number of row pairs

    for (int p = blockIdx.x; p < P; p += gridDim.x) {
        int i = p * 2 + half;
        bool valid = (i < L);
        int isafe = valid ? i : 0;

        const int* r = hex_idx + isafe * K;
        int j[K];
#pragma unroll
        for (int k = 0; k < K; k++) j[k] = __ldg(r + k);

        // 7 independent 256-bit gathers in flight (32-bit offsets).
        F8 v[K];
#pragma unroll
        for (int k = 0; k < K; k++)
            v[k] = ldg_el_256(x, (unsigned)j[k] * 2048u + coff);

        float m[8];
#pragma unroll
        for (int e = 0; e < 8; e++) {
            float t = v[0].f[e];
#pragma unroll
            for (int k = 1; k < K; k++) t = fmaxf(t, v[k].f[e]);
            m[e] = t;
        }

        if (valid) {
            float* op = out + (unsigned)i * 512u + (unsigned)c * 8u;
            stg_cs_128(op,     m[0], m[1], m[2], m[3]);
            stg_cs_128(op + 4, m[4], m[5], m[6], m[7]);
        }
    }
}

extern "C" void kernel_launch(void* const* d_in, const int* in_sizes, int n_in,
                              void* d_out, int out_size)
{
    const char* x   = (const char*)d_in[0];  // (N, 512) float32 rows
    const int*  idx = (const int*)d_in[1];   // (N, 7) int32
    float*      out = (float*)d_out;         // (L, 512) float32

    int L = out_size / 512;                  // 10242
    int P = (L + 1) / 2;                     // 5121 row pairs

    int grid = 148 * 8;                      // one full wave at occ=8
    if (grid > P) grid = P;

    hex_pool_kernel<<<grid, 128>>>(x, idx, out, L);
}

// round 6
// speedup vs baseline: 1.1530x; 1.1530x over previous
#include <cuda_runtime.h>

// out[i, c] = max_{k<7} x[hex_idx[i,k], c]  for i < L = out_size / 512
// hex_idx is int32 on disk (JAX downgrades int64 without x64 mode).
//
// R4 structure (best: 14.8us = LTS traffic floor, ~168MB @ ~11.4TB/s L2 cap):
// one-shot CTAs, 2 rows per 128-thread CTA, 64 threads x 32B chunks per row.
// 256-bit ld.global.nc.L2::evict_last gathers (pin x in L2), st.global.cs
// streaming stores (don't evict x). This round: 32-bit address math only.

static constexpr int K = 7;

struct F8 { float f[8]; };

__device__ __forceinline__ F8 ldg_el_256(const char* base, unsigned off) {
    unsigned long long r0, r1, r2, r3;
    asm("ld.global.nc.L2::evict_last.v4.b64 {%0,%1,%2,%3}, [%4];"
        : "=l"(r0), "=l"(r1), "=l"(r2), "=l"(r3)
        : "l"(base + off));
    F8 v;
    v.f[0] = __uint_as_float((unsigned)(r0 & 0xffffffffu));
    v.f[1] = __uint_as_float((unsigned)(r0 >> 32));
    v.f[2] = __uint_as_float((unsigned)(r1 & 0xffffffffu));
    v.f[3] = __uint_as_float((unsigned)(r1 >> 32));
    v.f[4] = __uint_as_float((unsigned)(r2 & 0xffffffffu));
    v.f[5] = __uint_as_float((unsigned)(r2 >> 32));
    v.f[6] = __uint_as_float((unsigned)(r3 & 0xffffffffu));
    v.f[7] = __uint_as_float((unsigned)(r3 >> 32));
    return v;
}

__device__ __forceinline__ void stg_cs_128(float* p, float a, float b, float c, float d) {
    asm volatile("st.global.cs.v4.f32 [%0], {%1,%2,%3,%4};"
                 :: "l"(p), "f"(a), "f"(b), "f"(c), "f"(d)
                 : "memory");
}

__global__ void __launch_bounds__(128)
hex_pool_kernel(const char* __restrict__ x,      // (N, 2048 bytes) rows
                const int*  __restrict__ hex_idx,
                float*      __restrict__ out,    // (L, 512) floats
                int L)
{
    // 2 rows per CTA: threads 0..63 -> row 2b, 64..127 -> row 2b+1.
    const int half = threadIdx.x >> 6;      // 0 or 1
    const int c    = threadIdx.x & 63;      // 32B chunk within row
    const int i    = blockIdx.x * 2 + half;
    if (i >= L) return;

    const int* r = hex_idx + i * K;
    int j[K];
#pragma unroll
    for (int k = 0; k < K; k++) j[k] = __ldg(r + k);

    const unsigned coff = (unsigned)c * 32u;

    // 7 independent 256-bit gathers in flight before any consumption.
    F8 v[K];
#pragma unroll
    for (int k = 0; k < K; k++)
        v[k] = ldg_el_256(x, (unsigned)j[k] * 2048u + coff);

    float m[8];
#pragma unroll
    for (int e = 0; e < 8; e++) {
        float t = v[0].f[e];
#pragma unroll
        for (int k = 1; k < K; k++) t = fmaxf(t, v[k].f[e]);
        m[e] = t;
    }

    float* op = out + (unsigned)i * 512u + (unsigned)c * 8u;
    stg_cs_128(op,     m[0], m[1], m[2], m[3]);
    stg_cs_128(op + 4, m[4], m[5], m[6], m[7]);
}

extern "C" void kernel_launch(void* const* d_in, const int* in_sizes, int n_in,
                              void* d_out, int out_size)
{
    const char* x   = (const char*)d_in[0];  // (N, 512) float32 rows
    const int*  idx = (const int*)d_in[1];   // (N, 7) int32
    float*      out = (float*)d_out;         // (L, 512) float32

    int L = out_size / 512;                  // 10242
    int grid = (L + 1) / 2;                  // 5121 one-shot CTAs

    hex_pool_kernel<<<grid, 128>>>(x, idx, out, L);
}